// round 1
// baseline (speedup 1.0000x reference)
#include <cuda_runtime.h>
#include <cstdint>
#include <math.h>

// ---------------------------------------------------------------------------
// Problem dims (fixed by the dataset)
// ---------------------------------------------------------------------------
#define BB 64
#define TT 512
#define DD 1024
#define HH 1024
#define SIXH (6 * HH)
#define FIVEH (5 * HH)
#define BTH (BB * TT * HH)      // 33,554,432
#define BH (BB * HH)            // 65,536

// Recurrent kernel config
#define NBLK 128                // persistent blocks (<=148 SMs -> co-resident)
#define JCH 8                   // hidden columns per block (NBLK*JCH = HH)
#define KC 64                   // k-chunk staged in smem

// ---------------------------------------------------------------------------
// Device scratch (static allocations only — no cudaMalloc allowed)
// ---------------------------------------------------------------------------
__device__ __align__(16) float g_pi[201326592];   // (B*T, 6H) = 805 MB, reused per layer
__device__ __align__(16) float g_y0[BTH];         // layer-0 output (B,T,H)
__device__ __align__(16) float g_Wpk[NBLK * HH * (5 * JCH)]; // packed recurrent weights
__device__ __align__(16) float g_hT[2][HH * BB];  // ping-pong h, transposed: [k][b]

__device__ unsigned g_barc = 0;
__device__ unsigned g_barf = 0;

__device__ __forceinline__ float sigf(float x) { return 1.f / (1.f + expf(-x)); }

// Epoch-based grid barrier (all NBLK blocks co-resident; 1 per time step)
__device__ __forceinline__ void grid_barrier(unsigned ep) {
    __syncthreads();
    if (threadIdx.x == 0) {
        __threadfence();
        unsigned old = atomicAdd(&g_barc, 1u);
        if (old == gridDim.x - 1) {
            g_barc = 0;
            __threadfence();
            atomicExch(&g_barf, ep);
        } else {
            while ((int)(*(volatile unsigned*)&g_barf - ep) < 0) {
                __nanosleep(32);
            }
        }
    }
    __syncthreads();
}

// ---------------------------------------------------------------------------
// Pack Ws (H x 5H row-major) -> g_Wpk[jb][k][w*5+g] = Ws[k][g*H + jb*8 + w]
// ---------------------------------------------------------------------------
__global__ void pack_kernel(const float* __restrict__ Ws) {
    int idx = blockIdx.x * blockDim.x + threadIdx.x;
    const int total = NBLK * HH * (5 * JCH);
    if (idx >= total) return;
    int jb = idx / (HH * 40);
    int rem = idx - jb * (HH * 40);
    int k = rem / 40;
    int c = rem - k * 40;
    int w = c / 5;
    int g = c - w * 5;
    g_Wpk[idx] = Ws[(size_t)k * FIVEH + g * HH + jb * JCH + w];
}

// ---------------------------------------------------------------------------
// fp32 SIMT GEMM: C(MxN) = A(MxK) * W(KxN), all row-major.
// 128x128 tile, bk=8, 256 threads, 8x8 micro-tile. Writes into g_pi.
// ---------------------------------------------------------------------------
__global__ __launch_bounds__(256, 2) void gemm_kernel(
    const float* __restrict__ A, const float* __restrict__ W,
    int M, int N, int K)
{
    __shared__ __align__(16) float As[8][128];
    __shared__ __align__(16) float Bs[8][128];

    const int tid = threadIdx.x;
    const int m0 = blockIdx.y * 128;
    const int n0 = blockIdx.x * 128;
    const int arow = tid >> 1;
    const int acol = (tid & 1) * 4;
    const int brow = tid >> 5;
    const int bcol = (tid & 31) * 4;
    const int ty = tid >> 4;
    const int tx = tid & 15;

    float acc[8][8];
    #pragma unroll
    for (int i = 0; i < 8; i++)
        #pragma unroll
        for (int j = 0; j < 8; j++) acc[i][j] = 0.f;

    const float* Ap = A + (size_t)(m0 + arow) * K + acol;
    const float* Wp = W + (size_t)brow * N + n0 + bcol;

    for (int k0 = 0; k0 < K; k0 += 8) {
        float4 av = *(const float4*)(Ap + k0);
        As[acol + 0][arow] = av.x;
        As[acol + 1][arow] = av.y;
        As[acol + 2][arow] = av.z;
        As[acol + 3][arow] = av.w;
        *(float4*)&Bs[brow][bcol] = *(const float4*)(Wp + (size_t)k0 * N);
        __syncthreads();
        #pragma unroll
        for (int kk = 0; kk < 8; kk++) {
            float a[8], b[8];
            *(float4*)&a[0] = *(const float4*)&As[kk][ty * 8];
            *(float4*)&a[4] = *(const float4*)&As[kk][ty * 8 + 4];
            *(float4*)&b[0] = *(const float4*)&Bs[kk][tx * 8];
            *(float4*)&b[4] = *(const float4*)&Bs[kk][tx * 8 + 4];
            #pragma unroll
            for (int i = 0; i < 8; i++)
                #pragma unroll
                for (int j = 0; j < 8; j++)
                    acc[i][j] = fmaf(a[i], b[j], acc[i][j]);
        }
        __syncthreads();
    }

    #pragma unroll
    for (int i = 0; i < 8; i++) {
        float* cp = g_pi + (size_t)(m0 + ty * 8 + i) * N + n0 + tx * 8;
        *(float4*)cp = make_float4(acc[i][0], acc[i][1], acc[i][2], acc[i][3]);
        *(float4*)(cp + 4) = make_float4(acc[i][4], acc[i][5], acc[i][6], acc[i][7]);
    }
}

// ---------------------------------------------------------------------------
// Persistent recurrent kernel: one launch covers all T time steps of a layer.
// Block jb owns hidden columns j = jb*8 .. jb*8+7 (one column per warp).
// Each lane owns batch rows (lane, lane+32) -> c,h kept in registers.
// h published transposed in global ping-pong buffers g_hT[.][k][b].
// ---------------------------------------------------------------------------
__global__ __launch_bounds__(256, 1) void rec_kernel(
    const float* __restrict__ bs, const int* __restrict__ lengths,
    float* __restrict__ y, float* __restrict__ outh, float* __restrict__ outc)
{
    __shared__ __align__(16) float hs[KC][BB];
    __shared__ __align__(16) float ws[KC][40];
    __shared__ unsigned s_base;

    const int tid = threadIdx.x;
    const int w = tid >> 5;
    const int lane = tid & 31;
    const int jb = blockIdx.x;
    const int j = jb * JCH + w;
    const int r0 = lane;
    const int r1 = lane + 32;

    if (tid == 0) s_base = *(volatile unsigned*)&g_barf;

    const int len0 = lengths[r0];
    const int len1 = lengths[r1];

    float bias[5];
    #pragma unroll
    for (int g = 0; g < 5; g++) bias[g] = bs[g * HH + j];

    // zero this block's columns of h buffer 0 (initial hidden state)
    g_hT[0][jb * (JCH * BB) + tid] = 0.f;
    g_hT[0][jb * (JCH * BB) + 256 + tid] = 0.f;

    __syncthreads();
    unsigned ep = s_base;
    grid_barrier(++ep);

    const float* Wb = g_Wpk + (size_t)jb * (HH * 40);

    float h0 = 0.f, h1 = 0.f, c0 = 0.f, c1 = 0.f;

    for (int t = 0; t < TT; t++) {
        const float* hTr = g_hT[t & 1];
        float* hTw = g_hT[(t + 1) & 1];

        // Prefetch input projections for this step (hidden under GEMM latency)
        float p0[6], p1[6];
        {
            const float* pr0 = g_pi + ((size_t)r0 * TT + t) * SIXH + j;
            const float* pr1 = g_pi + ((size_t)r1 * TT + t) * SIXH + j;
            #pragma unroll
            for (int g = 0; g < 6; g++) {
                p0[g] = pr0[g * HH];
                p1[g] = pr1[g * HH];
            }
        }

        float a0[5], a1[5];
        #pragma unroll
        for (int g = 0; g < 5; g++) { a0[g] = bias[g]; a1[g] = bias[g]; }

        for (int k0 = 0; k0 < HH; k0 += KC) {
            // stage h chunk (contiguous in transposed layout; bypass L1 w/ ldcg)
            const float4* hsrc = (const float4*)(hTr + k0 * BB);
            float4* hdst = (float4*)&hs[0][0];
            #pragma unroll
            for (int i = 0; i < 4; i++)
                hdst[tid + i * 256] = __ldcg(hsrc + tid + i * 256);
            // stage packed weight chunk (contiguous)
            const float4* wsrc = (const float4*)(Wb + (size_t)k0 * 40);
            float4* wdst = (float4*)&ws[0][0];
            #pragma unroll
            for (int i = 0; i < 3; i++) {
                int idx = tid + i * 256;
                if (idx < 640) wdst[idx] = wsrc[idx];
            }
            __syncthreads();
            #pragma unroll 4
            for (int kk = 0; kk < KC; kk++) {
                float hv0 = hs[kk][r0];
                float hv1 = hs[kk][r1];
                #pragma unroll
                for (int g = 0; g < 5; g++) {
                    float wv = ws[kk][w * 5 + g];
                    a0[g] = fmaf(wv, hv0, a0[g]);
                    a1[g] = fmaf(wv, hv1, a1[g]);
                }
            }
            __syncthreads();
        }

        // gate math, row r0
        {
            float ig = sigf(p0[0] + a0[0]);
            float fg = sigf(p0[1] + a0[1]);
            float mi = tanhf(p0[2] + a0[2]);
            float og = sigf(p0[3] + a0[3]);
            float cn = ig * mi + fg * c0;
            float o = og * tanhf(cn);
            float hg = sigf(p0[4] + a0[4]);
            o = hg * o + (1.f - hg) * p0[5];
            bool v = (t < len0);
            if (v) { c0 = cn; h0 = o; }
            y[((size_t)r0 * TT + t) * HH + j] = v ? o : 0.f;
        }
        // gate math, row r1
        {
            float ig = sigf(p1[0] + a1[0]);
            float fg = sigf(p1[1] + a1[1]);
            float mi = tanhf(p1[2] + a1[2]);
            float og = sigf(p1[3] + a1[3]);
            float cn = ig * mi + fg * c1;
            float o = og * tanhf(cn);
            float hg = sigf(p1[4] + a1[4]);
            o = hg * o + (1.f - hg) * p1[5];
            bool v = (t < len1);
            if (v) { c1 = cn; h1 = o; }
            y[((size_t)r1 * TT + t) * HH + j] = v ? o : 0.f;
        }

        // publish h for next step (other buffer -> single barrier per step)
        __stcg(&hTw[j * BB + r0], h0);
        __stcg(&hTw[j * BB + r1], h1);

        grid_barrier(++ep);
    }

    // final states
    outh[(size_t)r0 * HH + j] = h0;
    outh[(size_t)r1 * HH + j] = h1;
    outc[(size_t)r0 * HH + j] = c0;
    outc[(size_t)r1 * HH + j] = c1;
}

// ---------------------------------------------------------------------------
// Launcher
// ---------------------------------------------------------------------------
extern "C" void kernel_launch(void* const* d_in, const int* in_sizes, int n_in,
                              void* d_out, int out_size)
{
    (void)in_sizes; (void)n_in; (void)out_size;
    const float* x   = (const float*)d_in[0];
    const int*   len = (const int*)d_in[1];
    const float* Wi0 = (const float*)d_in[2];
    const float* Ws0 = (const float*)d_in[3];
    const float* bs0 = (const float*)d_in[4];
    const float* Wi1 = (const float*)d_in[5];
    const float* Ws1 = (const float*)d_in[6];
    const float* bs1 = (const float*)d_in[7];
    float* out = (float*)d_out;

    float* y0_ptr = nullptr;
    cudaGetSymbolAddress((void**)&y0_ptr, g_y0);

    float* outh = out + BTH;            // (2,B,H)
    float* outc = out + BTH + 2 * BH;   // (2,B,H)

    const int pack_total = NBLK * HH * (5 * JCH);
    dim3 ggrid(SIXH / 128, (BB * TT) / 128);

    // ---- layer 0 ----
    pack_kernel<<<(pack_total + 255) / 256, 256>>>(Ws0);
    gemm_kernel<<<ggrid, 256>>>(x, Wi0, BB * TT, SIXH, DD);
    rec_kernel<<<NBLK, 256>>>(bs0, len, y0_ptr, outh, outc);

    // ---- layer 1 ----
    pack_kernel<<<(pack_total + 255) / 256, 256>>>(Ws1);
    gemm_kernel<<<ggrid, 256>>>(y0_ptr, Wi1, BB * TT, SIXH, HH);
    rec_kernel<<<NBLK, 256>>>(bs1, len, out, outh + BH, outc + BH);
}